// round 2
// baseline (speedup 1.0000x reference)
#include <cuda_runtime.h>
#include <cuda_bf16.h>
#include <cstdint>
#include <math.h>

#define T_TOK 16384
#define HDIM  2048
#define FDIM  256
#define NEXP  12
#define CAP   1707
#define CAPP  1792   // 14 * 128
#define LG2T  14

// ---------------- scratch (device globals; no allocs allowed) ----------------
__device__ float g_rw [T_TOK * 2];
__device__ int   g_sel[T_TOK * 2];
__device__ int   g_tok[NEXP * CAPP];
__device__ float g_wgt[NEXP * CAPP];
__device__ int   g_cnt[NEXP];
__device__ float g_h  [NEXP * CAPP * FDIM];   // ~22 MB intermediate activations

// ---------------- helpers ----------------
__device__ __forceinline__ uint32_t f2tf(float f) {
    uint32_t u;
    asm("cvt.rna.tf32.f32 %0, %1;" : "=r"(u) : "f"(f));
    return u;
}

__device__ __forceinline__ void mma_tf32(float& d0, float& d1, float& d2, float& d3,
                                         uint32_t a0, uint32_t a1, uint32_t a2, uint32_t a3,
                                         uint32_t b0, uint32_t b1) {
    asm volatile(
        "mma.sync.aligned.m16n8k8.row.col.f32.tf32.tf32.f32 "
        "{%0,%1,%2,%3}, {%4,%5,%6,%7}, {%8,%9}, {%0,%1,%2,%3};"
        : "+f"(d0), "+f"(d1), "+f"(d2), "+f"(d3)
        : "r"(a0), "r"(a1), "r"(a2), "r"(a3), "r"(b0), "r"(b1));
}

// ---------------- kernel 0: zero output ----------------
__global__ void k_zero(float4* out, int n4) {
    int i = blockIdx.x * blockDim.x + threadIdx.x;
    if (i < n4) out[i] = make_float4(0.f, 0.f, 0.f, 0.f);
}

// ---------------- kernel 1: gating (one warp per token) ----------------
__global__ __launch_bounds__(256) void k_gate(const float* __restrict__ x,
                                              const float* __restrict__ gw) {
    int warp = (blockIdx.x * blockDim.x + threadIdx.x) >> 5;
    int lane = threadIdx.x & 31;
    if (warp >= T_TOK) return;
    const float* xr = x + (size_t)warp * HDIM;

    float acc[NEXP];
#pragma unroll
    for (int e = 0; e < NEXP; e++) acc[e] = 0.f;

    for (int h = lane; h < HDIM; h += 32) {
        float xv = xr[h];
#pragma unroll
        for (int e = 0; e < NEXP; e++) acc[e] += xv * gw[e * HDIM + h];
    }
#pragma unroll
    for (int e = 0; e < NEXP; e++) {
#pragma unroll
        for (int off = 16; off; off >>= 1)
            acc[e] += __shfl_xor_sync(0xffffffffu, acc[e], off);
    }
    if (lane == 0) {
        float m1 = -1e30f, m2 = -1e30f;
        int i1 = 0, i2 = 0;
#pragma unroll
        for (int e = 0; e < NEXP; e++) {
            float v = acc[e];
            if (v > m1)      { m2 = m1; i2 = i1; m1 = v; i1 = e; }
            else if (v > m2) { m2 = v;  i2 = e; }
        }
        // renormalized top-2 weights == softmax over the two top logits
        float w1v = 1.f / (1.f + expf(m2 - m1));
        g_sel[warp * 2 + 0] = i1;
        g_sel[warp * 2 + 1] = i2;
        g_rw [warp * 2 + 0] = w1v;
        g_rw [warp * 2 + 1] = 1.f - w1v;
    }
}

// ---------------- kernel 2: order-preserving dispatch scan ----------------
// Entry i in [0, 2T): k = i>>14, t = i & (T-1), expert = sel[t][k].
// Positions assigned in i-order; entries with pos >= CAP are dropped
// (exactly matching the reference's cumsum-based capacity logic).
__global__ __launch_bounds__(1024) void k_scan() {
    __shared__ int s[1024 * NEXP];   // 48 KB
    int j = threadIdx.x;

    // clear dispatch tables (pad rows -> token 0, weight 0)
    for (int i = j; i < NEXP * CAPP; i += 1024) {
        g_tok[i] = 0;
        g_wgt[i] = 0.f;
    }

    int base = j * 32;
    int myexp[32];
    int cnt[NEXP];
#pragma unroll
    for (int e = 0; e < NEXP; e++) cnt[e] = 0;

#pragma unroll
    for (int q = 0; q < 32; q++) {
        int i = base + q;
        int t = i & (T_TOK - 1);
        int k = i >> LG2T;
        int e = g_sel[t * 2 + k];
        myexp[q] = e;
#pragma unroll
        for (int ee = 0; ee < NEXP; ee++) cnt[ee] += (ee == e);
    }

    int run[NEXP];
#pragma unroll
    for (int e = 0; e < NEXP; e++) { run[e] = cnt[e]; s[j * NEXP + e] = run[e]; }
    __syncthreads();

    for (int d = 1; d < 1024; d <<= 1) {
        int tmp[NEXP];
#pragma unroll
        for (int e = 0; e < NEXP; e++) tmp[e] = (j >= d) ? s[(j - d) * NEXP + e] : 0;
        __syncthreads();
#pragma unroll
        for (int e = 0; e < NEXP; e++) { run[e] += tmp[e]; s[j * NEXP + e] = run[e]; }
        __syncthreads();
    }

    if (j == 1023) {
#pragma unroll
        for (int e = 0; e < NEXP; e++) g_cnt[e] = run[e];
    }

    int off[NEXP];
#pragma unroll
    for (int e = 0; e < NEXP; e++) off[e] = run[e] - cnt[e];   // exclusive start

#pragma unroll
    for (int q = 0; q < 32; q++) {
        int i = base + q;
        int t = i & (T_TOK - 1);
        int k = i >> LG2T;
        int e = myexp[q];
        int pos = 0;
#pragma unroll
        for (int ee = 0; ee < NEXP; ee++)
            if (ee == e) { pos = off[ee]; off[ee]++; }
        if (pos < CAP) {
            g_tok[e * CAPP + pos] = t;
            g_wgt[e * CAPP + pos] = g_rw[t * 2 + k];
        }
    }
}

// ---------------- kernel 3: GEMM1 (x_gathered @ [w1;w3]^T, silu(a*b)) ----------------
// NOTE: reference computes h = silu((x@w1^T) * (x@w3^T)) — silu AFTER the product.
// Block tile: 128 (rows) x 64 (F cols), BK=32, 8 warps (4x2), warp tile 32x32.
__global__ __launch_bounds__(256) void k_ffn1(const float* __restrict__ x,
                                              const float* __restrict__ w1,
                                              const float* __restrict__ w3) {
    int e    = blockIdx.z;
    int row0 = blockIdx.x * 128;
    int n0   = blockIdx.y * 64;
    int ne   = min(g_cnt[e], CAP);
    float* hout = g_h + (size_t)e * CAPP * FDIM;

    if (row0 >= ne) {
        // fully-padded tile: write zeros so GEMM2 reads finite data
        for (int i = threadIdx.x; i < 128 * 64; i += 256) {
            int r = i >> 6, c = i & 63;
            hout[(size_t)(row0 + r) * FDIM + n0 + c] = 0.f;
        }
        return;
    }

    __shared__ uint32_t As[128 * 36];
    __shared__ uint32_t Bs[2][64 * 36];
    __shared__ int s_tok[128];

    int tid = threadIdx.x;
    if (tid < 128) s_tok[tid] = g_tok[e * CAPP + row0 + tid];
    __syncthreads();

    int warp = tid >> 5, lane = tid & 31;
    int wm = warp >> 1, wn = warp & 1;
    int g = lane >> 2, tg = lane & 3;

    float accA[2][4][4], accB[2][4][4];
#pragma unroll
    for (int mi = 0; mi < 2; mi++)
#pragma unroll
        for (int ni = 0; ni < 4; ni++)
#pragma unroll
            for (int q = 0; q < 4; q++) { accA[mi][ni][q] = 0.f; accB[mi][ni][q] = 0.f; }

    const float* w1e = w1 + (size_t)e * FDIM * HDIM;
    const float* w3e = w3 + (size_t)e * FDIM * HDIM;

    for (int k0 = 0; k0 < HDIM; k0 += 32) {
        // stage A: 128x32 gathered rows of x (1024 float4, 4/thread)
#pragma unroll
        for (int r4 = 0; r4 < 4; r4++) {
            int idx = tid + 256 * r4;
            int row = idx >> 3, c4 = idx & 7;
            float4 v = *(const float4*)(x + (size_t)s_tok[row] * HDIM + k0 + c4 * 4);
            uint32_t* dst = &As[row * 36 + c4 * 4];
            dst[0] = f2tf(v.x); dst[1] = f2tf(v.y); dst[2] = f2tf(v.z); dst[3] = f2tf(v.w);
        }
        // stage B: w1 and w3 tiles, 64x32 each (1024 float4 total, 4/thread)
#pragma unroll
        for (int r4 = 0; r4 < 4; r4++) {
            int idx = tid + 256 * r4;
            int m = idx >> 9, rem = idx & 511;
            int n = rem >> 3, c4 = rem & 7;
            const float* wsrc = (m == 0) ? w1e : w3e;
            float4 v = *(const float4*)(wsrc + (size_t)(n0 + n) * HDIM + k0 + c4 * 4);
            uint32_t* dst = &Bs[m][n * 36 + c4 * 4];
            dst[0] = f2tf(v.x); dst[1] = f2tf(v.y); dst[2] = f2tf(v.z); dst[3] = f2tf(v.w);
        }
        __syncthreads();

#pragma unroll
        for (int kk = 0; kk < 4; kk++) {
            uint32_t a[2][4];
#pragma unroll
            for (int mi = 0; mi < 2; mi++) {
                int r = wm * 32 + mi * 16;
                a[mi][0] = As[(r + g)     * 36 + kk * 8 + tg];
                a[mi][1] = As[(r + 8 + g) * 36 + kk * 8 + tg];
                a[mi][2] = As[(r + g)     * 36 + kk * 8 + tg + 4];
                a[mi][3] = As[(r + 8 + g) * 36 + kk * 8 + tg + 4];
            }
#pragma unroll
            for (int ni = 0; ni < 4; ni++) {
                int n = wn * 32 + ni * 8 + g;
                uint32_t b0 = Bs[0][n * 36 + kk * 8 + tg];
                uint32_t b1 = Bs[0][n * 36 + kk * 8 + tg + 4];
                uint32_t c0 = Bs[1][n * 36 + kk * 8 + tg];
                uint32_t c1 = Bs[1][n * 36 + kk * 8 + tg + 4];
#pragma unroll
                for (int mi = 0; mi < 2; mi++) {
                    mma_tf32(accA[mi][ni][0], accA[mi][ni][1], accA[mi][ni][2], accA[mi][ni][3],
                             a[mi][0], a[mi][1], a[mi][2], a[mi][3], b0, b1);
                    mma_tf32(accB[mi][ni][0], accB[mi][ni][1], accB[mi][ni][2], accB[mi][ni][3],
                             a[mi][0], a[mi][1], a[mi][2], a[mi][3], c0, c1);
                }
            }
        }
        __syncthreads();
    }

    // epilogue: h = silu(a * b) = p * sigmoid(p), p = a*b   (matches reference!)
#pragma unroll
    for (int mi = 0; mi < 2; mi++) {
#pragma unroll
        for (int ni = 0; ni < 4; ni++) {
            int rbase = row0 + wm * 32 + mi * 16 + g;
            int cbase = n0 + wn * 32 + ni * 8 + tg * 2;
#pragma unroll
            for (int h = 0; h < 2; h++) {
                int r = rbase + h * 8;
                float p0 = accA[mi][ni][h * 2 + 0] * accB[mi][ni][h * 2 + 0];
                float p1 = accA[mi][ni][h * 2 + 1] * accB[mi][ni][h * 2 + 1];
                float s0 = p0 / (1.f + expf(-p0));
                float s1 = p1 / (1.f + expf(-p1));
                hout[(size_t)r * FDIM + cbase]     = s0;
                hout[(size_t)r * FDIM + cbase + 1] = s1;
            }
        }
    }
}

// ---------------- kernel 4: GEMM2 (h @ w2^T) + weighted atomic scatter ----------------
__global__ __launch_bounds__(256) void k_ffn2(const float* __restrict__ w2,
                                              float* __restrict__ out) {
    int e    = blockIdx.z;
    int row0 = blockIdx.x * 128;
    int n0   = blockIdx.y * 64;
    int ne   = min(g_cnt[e], CAP);
    if (row0 >= ne) return;

    __shared__ uint32_t As[128 * 36];
    __shared__ uint32_t Bs[64 * 36];
    __shared__ int   s_tok[128];
    __shared__ float s_wgt[128];

    int tid = threadIdx.x;
    if (tid < 128) {
        s_tok[tid] = g_tok[e * CAPP + row0 + tid];
        s_wgt[tid] = g_wgt[e * CAPP + row0 + tid];
    }
    __syncthreads();

    int warp = tid >> 5, lane = tid & 31;
    int wm = warp >> 1, wn = warp & 1;
    int g = lane >> 2, tg = lane & 3;

    float acc[2][4][4];
#pragma unroll
    for (int mi = 0; mi < 2; mi++)
#pragma unroll
        for (int ni = 0; ni < 4; ni++)
#pragma unroll
            for (int q = 0; q < 4; q++) acc[mi][ni][q] = 0.f;

    const float* hin = g_h + (size_t)e * CAPP * FDIM;
    const float* w2e = w2 + (size_t)e * HDIM * FDIM;

    for (int k0 = 0; k0 < FDIM; k0 += 32) {
#pragma unroll
        for (int r4 = 0; r4 < 4; r4++) {
            int idx = tid + 256 * r4;
            int row = idx >> 3, c4 = idx & 7;
            float4 v = *(const float4*)(hin + (size_t)(row0 + row) * FDIM + k0 + c4 * 4);
            uint32_t* dst = &As[row * 36 + c4 * 4];
            dst[0] = f2tf(v.x); dst[1] = f2tf(v.y); dst[2] = f2tf(v.z); dst[3] = f2tf(v.w);
        }
#pragma unroll
        for (int r4 = 0; r4 < 2; r4++) {
            int idx = tid + 256 * r4;
            int n = idx >> 3, c4 = idx & 7;
            float4 v = *(const float4*)(w2e + (size_t)(n0 + n) * FDIM + k0 + c4 * 4);
            uint32_t* dst = &Bs[n * 36 + c4 * 4];
            dst[0] = f2tf(v.x); dst[1] = f2tf(v.y); dst[2] = f2tf(v.z); dst[3] = f2tf(v.w);
        }
        __syncthreads();

#pragma unroll
        for (int kk = 0; kk < 4; kk++) {
            uint32_t a[2][4];
#pragma unroll
            for (int mi = 0; mi < 2; mi++) {
                int r = wm * 32 + mi * 16;
                a[mi][0] = As[(r + g)     * 36 + kk * 8 + tg];
                a[mi][1] = As[(r + 8 + g) * 36 + kk * 8 + tg];
                a[mi][2] = As[(r + g)     * 36 + kk * 8 + tg + 4];
                a[mi][3] = As[(r + 8 + g) * 36 + kk * 8 + tg + 4];
            }
#pragma unroll
            for (int ni = 0; ni < 4; ni++) {
                int n = wn * 32 + ni * 8 + g;
                uint32_t b0 = Bs[n * 36 + kk * 8 + tg];
                uint32_t b1 = Bs[n * 36 + kk * 8 + tg + 4];
#pragma unroll
                for (int mi = 0; mi < 2; mi++)
                    mma_tf32(acc[mi][ni][0], acc[mi][ni][1], acc[mi][ni][2], acc[mi][ni][3],
                             a[mi][0], a[mi][1], a[mi][2], a[mi][3], b0, b1);
            }
        }
        __syncthreads();
    }

    // epilogue: weighted atomic scatter into out (<=2 adds per output element)
#pragma unroll
    for (int mi = 0; mi < 2; mi++) {
#pragma unroll
        for (int ni = 0; ni < 4; ni++) {
            int cbase = n0 + wn * 32 + ni * 8 + tg * 2;
#pragma unroll
            for (int h = 0; h < 2; h++) {
                int rl = wm * 32 + mi * 16 + g + h * 8;
                float w = s_wgt[rl];
                if (w != 0.f) {
                    int tok = s_tok[rl];
                    atomicAdd(&out[(size_t)tok * HDIM + cbase],     acc[mi][ni][h * 2 + 0] * w);
                    atomicAdd(&out[(size_t)tok * HDIM + cbase + 1], acc[mi][ni][h * 2 + 1] * w);
                }
            }
        }
    }
}

// ---------------- launch ----------------
extern "C" void kernel_launch(void* const* d_in, const int* in_sizes, int n_in,
                              void* d_out, int out_size) {
    // Robust input identification by element count (order-independent):
    //   x: 4*4096*2048 = 33554432, gate_w: 12*2048 = 24576,
    //   w1/w2/w3: 12*256*2048 = 6291456 each (relative order preserved).
    const float* x  = nullptr;
    const float* gw = nullptr;
    const float* wbig[3] = {nullptr, nullptr, nullptr};
    int nbig = 0;
    for (int i = 0; i < n_in; i++) {
        long long sz = in_sizes[i];
        if (sz == (long long)T_TOK * HDIM)           x = (const float*)d_in[i];
        else if (sz == (long long)NEXP * HDIM)       gw = (const float*)d_in[i];
        else if (nbig < 3)                           wbig[nbig++] = (const float*)d_in[i];
    }
    const float* w1 = wbig[0];
    const float* w2 = wbig[1];
    const float* w3 = wbig[2];
    float* out = (float*)d_out;

    int n4 = T_TOK * HDIM / 4;
    k_zero<<<(n4 + 255) / 256, 256>>>((float4*)out, n4);
    k_gate<<<T_TOK / 8, 256>>>(x, gw);
    k_scan<<<1, 1024>>>();
    k_ffn1<<<dim3(CAPP / 128, FDIM / 64, NEXP), 256>>>(x, w1, w3);
    k_ffn2<<<dim3(CAPP / 128, HDIM / 64, NEXP), 256>>>(w2, out);
}

// round 3
// speedup vs baseline: 1.5154x; 1.5154x over previous
#include <cuda_runtime.h>
#include <cuda_bf16.h>
#include <cstdint>
#include <math.h>

#define T_TOK 16384
#define HDIM  2048
#define FDIM  256
#define NEXP  12
#define CAP   1707
#define CAPP  1792   // 14 * 128
#define LG2T  14

// ---------------- scratch (device globals; no allocs allowed) ----------------
__device__ float g_rw [T_TOK * 2];
__device__ int   g_sel[T_TOK * 2];
__device__ int   g_tok[NEXP * CAPP];
__device__ float g_wgt[NEXP * CAPP];
__device__ int   g_cnt[NEXP];
__device__ __align__(16) uint32_t g_h  [NEXP * CAPP * FDIM];      // tf32 intermediate
__device__ __align__(16) uint32_t g_w1t[NEXP * FDIM * HDIM];      // tf32 weights
__device__ __align__(16) uint32_t g_w2t[NEXP * HDIM * FDIM];
__device__ __align__(16) uint32_t g_w3t[NEXP * FDIM * HDIM];

// ---------------- helpers ----------------
__device__ __forceinline__ uint32_t f2tf(float f) {
    uint32_t u;
    asm("cvt.rna.tf32.f32 %0, %1;" : "=r"(u) : "f"(f));
    return u;
}

__device__ __forceinline__ void mma_tf32(float& d0, float& d1, float& d2, float& d3,
                                         uint32_t a0, uint32_t a1, uint32_t a2, uint32_t a3,
                                         uint32_t b0, uint32_t b1) {
    asm volatile(
        "mma.sync.aligned.m16n8k8.row.col.f32.tf32.tf32.f32 "
        "{%0,%1,%2,%3}, {%4,%5,%6,%7}, {%8,%9}, {%0,%1,%2,%3};"
        : "+f"(d0), "+f"(d1), "+f"(d2), "+f"(d3)
        : "r"(a0), "r"(a1), "r"(a2), "r"(a3), "r"(b0), "r"(b1));
}

__device__ __forceinline__ uint32_t sptr(const void* p) {
    return (uint32_t)__cvta_generic_to_shared(p);
}

#define CP16(dst_u32, src_ptr) \
    asm volatile("cp.async.cg.shared.global [%0], [%1], 16;" :: "r"(dst_u32), "l"(src_ptr))
#define CP_COMMIT() asm volatile("cp.async.commit_group;")
#define CP_WAIT1()  asm volatile("cp.async.wait_group 1;")

// ---------------- kernel 0: zero output ----------------
__global__ void k_zero(float4* out, int n4) {
    int i = blockIdx.x * blockDim.x + threadIdx.x;
    if (i < n4) out[i] = make_float4(0.f, 0.f, 0.f, 0.f);
}

// ---------------- kernel 0b: convert one weight tensor fp32 -> tf32 ----------------
__global__ void k_cvt(const float4* __restrict__ src, uint4* __restrict__ dst, int n4) {
    int i = blockIdx.x * blockDim.x + threadIdx.x;
    if (i < n4) {
        float4 v = src[i];
        uint4 u;
        u.x = f2tf(v.x); u.y = f2tf(v.y); u.z = f2tf(v.z); u.w = f2tf(v.w);
        dst[i] = u;
    }
}

// ---------------- kernel 1: gating (one warp per token) ----------------
__global__ __launch_bounds__(256) void k_gate(const float* __restrict__ x,
                                              const float* __restrict__ gw) {
    int warp = (blockIdx.x * blockDim.x + threadIdx.x) >> 5;
    int lane = threadIdx.x & 31;
    if (warp >= T_TOK) return;
    const float4* xr = (const float4*)(x + (size_t)warp * HDIM);

    float acc[NEXP];
#pragma unroll
    for (int e = 0; e < NEXP; e++) acc[e] = 0.f;

    for (int h4 = lane; h4 < HDIM / 4; h4 += 32) {
        float4 xv = xr[h4];
#pragma unroll
        for (int e = 0; e < NEXP; e++) {
            float4 gv = ((const float4*)(gw + e * HDIM))[h4];
            acc[e] += xv.x * gv.x + xv.y * gv.y + xv.z * gv.z + xv.w * gv.w;
        }
    }
#pragma unroll
    for (int e = 0; e < NEXP; e++) {
#pragma unroll
        for (int off = 16; off; off >>= 1)
            acc[e] += __shfl_xor_sync(0xffffffffu, acc[e], off);
    }
    if (lane == 0) {
        float m1 = -1e30f, m2 = -1e30f;
        int i1 = 0, i2 = 0;
#pragma unroll
        for (int e = 0; e < NEXP; e++) {
            float v = acc[e];
            if (v > m1)      { m2 = m1; i2 = i1; m1 = v; i1 = e; }
            else if (v > m2) { m2 = v;  i2 = e; }
        }
        float w1v = 1.f / (1.f + expf(m2 - m1));
        g_sel[warp * 2 + 0] = i1;
        g_sel[warp * 2 + 1] = i2;
        g_rw [warp * 2 + 0] = w1v;
        g_rw [warp * 2 + 1] = 1.f - w1v;
    }
}

// ---------------- kernel 2: order-preserving dispatch scan ----------------
__global__ __launch_bounds__(1024) void k_scan() {
    __shared__ int s[1024 * NEXP];   // 48 KB
    int j = threadIdx.x;

    for (int i = j; i < NEXP * CAPP; i += 1024) {
        g_tok[i] = 0;
        g_wgt[i] = 0.f;
    }

    int base = j * 32;
    int myexp[32];
    int cnt[NEXP];
#pragma unroll
    for (int e = 0; e < NEXP; e++) cnt[e] = 0;

#pragma unroll
    for (int q = 0; q < 32; q++) {
        int i = base + q;
        int t = i & (T_TOK - 1);
        int k = i >> LG2T;
        int e = g_sel[t * 2 + k];
        myexp[q] = e;
#pragma unroll
        for (int ee = 0; ee < NEXP; ee++) cnt[ee] += (ee == e);
    }

    int run[NEXP];
#pragma unroll
    for (int e = 0; e < NEXP; e++) { run[e] = cnt[e]; s[j * NEXP + e] = run[e]; }
    __syncthreads();

    for (int d = 1; d < 1024; d <<= 1) {
        int tmp[NEXP];
#pragma unroll
        for (int e = 0; e < NEXP; e++) tmp[e] = (j >= d) ? s[(j - d) * NEXP + e] : 0;
        __syncthreads();
#pragma unroll
        for (int e = 0; e < NEXP; e++) { run[e] += tmp[e]; s[j * NEXP + e] = run[e]; }
        __syncthreads();
    }

    if (j == 1023) {
#pragma unroll
        for (int e = 0; e < NEXP; e++) g_cnt[e] = run[e];
    }

    int off[NEXP];
#pragma unroll
    for (int e = 0; e < NEXP; e++) off[e] = run[e] - cnt[e];

#pragma unroll
    for (int q = 0; q < 32; q++) {
        int i = base + q;
        int t = i & (T_TOK - 1);
        int k = i >> LG2T;
        int e = myexp[q];
        int pos = 0;
#pragma unroll
        for (int ee = 0; ee < NEXP; ee++)
            if (ee == e) { pos = off[ee]; off[ee]++; }
        if (pos < CAP) {
            g_tok[e * CAPP + pos] = t;
            g_wgt[e * CAPP + pos] = g_rw[t * 2 + k];
        }
    }
}

// ---------------- kernel 3: GEMM1 (cp.async 2-stage pipeline) ----------------
// h = silu((x@w1^T) * (x@w3^T)); A = gathered x (fp32, per-use cvt), B = tf32 weights.
// Block 128x64, BK=32, 8 warps (4x2), warp tile 32x32, two B operands share A.
#define F1_AST 4608            // 128*36 uint32
#define F1_BST 4608            // 2*64*36
#define F1_STG (F1_AST + F1_BST)
#define F1_SMEM (2 * F1_STG * 4)

__global__ __launch_bounds__(256, 2) void k_ffn1(const float* __restrict__ x) {
    extern __shared__ uint32_t sm[];
    __shared__ int s_tok[128];

    int e    = blockIdx.z;
    int row0 = blockIdx.x * 128;
    int n0   = blockIdx.y * 64;
    int ne   = min(g_cnt[e], CAP);
    uint32_t* hout = g_h + (size_t)e * CAPP * FDIM;

    if (row0 >= ne) {
        for (int i = threadIdx.x; i < 128 * 64; i += 256) {
            int r = i >> 6, c = i & 63;
            hout[(size_t)(row0 + r) * FDIM + n0 + c] = 0u;
        }
        return;
    }

    int tid = threadIdx.x;
    if (tid < 128) s_tok[tid] = g_tok[e * CAPP + row0 + tid];
    __syncthreads();

    const uint32_t* w1e = g_w1t + (size_t)e * FDIM * HDIM;
    const uint32_t* w3e = g_w3t + (size_t)e * FDIM * HDIM;

    // per-thread load descriptors (4 A chunks + 4 B chunks of 16B each)
    int a_row[4], a_c4[4];
    const uint32_t* b_src[4];
    uint32_t a_dst[4], b_dst[4];
#pragma unroll
    for (int r4 = 0; r4 < 4; r4++) {
        int idx = tid + 256 * r4;
        a_row[r4] = idx >> 3;
        a_c4 [r4] = idx & 7;
        a_dst[r4] = sptr(sm + a_row[r4] * 36 + a_c4[r4] * 4);
        int m = idx >> 9, rem = idx & 511;
        int n = rem >> 3, c4 = rem & 7;
        b_src[r4] = ((m == 0) ? w1e : w3e) + (size_t)(n0 + n) * HDIM + c4 * 4;
        b_dst[r4] = sptr(sm + F1_AST + (m * 64 + n) * 36 + c4 * 4);
    }

    int warp = tid >> 5, lane = tid & 31;
    int wm = warp >> 1, wn = warp & 1;
    int g = lane >> 2, tg = lane & 3;

    float accA[2][4][4], accB[2][4][4];
#pragma unroll
    for (int mi = 0; mi < 2; mi++)
#pragma unroll
        for (int ni = 0; ni < 4; ni++)
#pragma unroll
            for (int q = 0; q < 4; q++) { accA[mi][ni][q] = 0.f; accB[mi][ni][q] = 0.f; }

    // prologue: stage tiles 0 and 1
#pragma unroll
    for (int t = 0; t < 2; t++) {
        int k0 = t * 32;
        uint32_t off = t * F1_STG * 4;
#pragma unroll
        for (int r4 = 0; r4 < 4; r4++) {
            CP16(a_dst[r4] + off, x + (size_t)s_tok[a_row[r4]] * HDIM + k0 + a_c4[r4] * 4);
            CP16(b_dst[r4] + off, b_src[r4] + k0);
        }
        CP_COMMIT();
    }

#pragma unroll 1
    for (int t = 0; t < HDIM / 32; t++) {
        CP_WAIT1();
        __syncthreads();
        int p = t & 1;
        const uint32_t* As = sm + p * F1_STG;
        const uint32_t* Bs = As + F1_AST;

#pragma unroll
        for (int kk = 0; kk < 4; kk++) {
            uint32_t a[2][4];
#pragma unroll
            for (int mi = 0; mi < 2; mi++) {
                int r = wm * 32 + mi * 16;
                a[mi][0] = f2tf(__uint_as_float(As[(r + g)     * 36 + kk * 8 + tg]));
                a[mi][1] = f2tf(__uint_as_float(As[(r + 8 + g) * 36 + kk * 8 + tg]));
                a[mi][2] = f2tf(__uint_as_float(As[(r + g)     * 36 + kk * 8 + tg + 4]));
                a[mi][3] = f2tf(__uint_as_float(As[(r + 8 + g) * 36 + kk * 8 + tg + 4]));
            }
#pragma unroll
            for (int ni = 0; ni < 4; ni++) {
                int n = wn * 32 + ni * 8 + g;
                uint32_t b0 = Bs[n * 36 + kk * 8 + tg];
                uint32_t b1 = Bs[n * 36 + kk * 8 + tg + 4];
                uint32_t c0 = Bs[(64 + n) * 36 + kk * 8 + tg];
                uint32_t c1 = Bs[(64 + n) * 36 + kk * 8 + tg + 4];
#pragma unroll
                for (int mi = 0; mi < 2; mi++) {
                    mma_tf32(accA[mi][ni][0], accA[mi][ni][1], accA[mi][ni][2], accA[mi][ni][3],
                             a[mi][0], a[mi][1], a[mi][2], a[mi][3], b0, b1);
                    mma_tf32(accB[mi][ni][0], accB[mi][ni][1], accB[mi][ni][2], accB[mi][ni][3],
                             a[mi][0], a[mi][1], a[mi][2], a[mi][3], c0, c1);
                }
            }
        }
        __syncthreads();

        int tn = t + 2;
        if (tn < HDIM / 32) {
            int k0 = tn * 32;
            uint32_t off = p * F1_STG * 4;
#pragma unroll
            for (int r4 = 0; r4 < 4; r4++) {
                CP16(a_dst[r4] + off, x + (size_t)s_tok[a_row[r4]] * HDIM + k0 + a_c4[r4] * 4);
                CP16(b_dst[r4] + off, b_src[r4] + k0);
            }
        }
        CP_COMMIT();
    }

    // epilogue: h = silu(a*b) stored as tf32
#pragma unroll
    for (int mi = 0; mi < 2; mi++) {
#pragma unroll
        for (int ni = 0; ni < 4; ni++) {
            int rbase = row0 + wm * 32 + mi * 16 + g;
            int cbase = n0 + wn * 32 + ni * 8 + tg * 2;
#pragma unroll
            for (int h = 0; h < 2; h++) {
                int r = rbase + h * 8;
                float p0 = accA[mi][ni][h * 2 + 0] * accB[mi][ni][h * 2 + 0];
                float p1 = accA[mi][ni][h * 2 + 1] * accB[mi][ni][h * 2 + 1];
                float s0 = p0 / (1.f + expf(-p0));
                float s1 = p1 / (1.f + expf(-p1));
                hout[(size_t)r * FDIM + cbase]     = f2tf(s0);
                hout[(size_t)r * FDIM + cbase + 1] = f2tf(s1);
            }
        }
    }
}

// ---------------- kernel 4: GEMM2 (cp.async 2-stage) + weighted atomic scatter ----------------
#define F2_AST 4608            // 128*36
#define F2_BST 2304            // 64*36
#define F2_STG (F2_AST + F2_BST)
#define F2_SMEM (2 * F2_STG * 4)

__global__ __launch_bounds__(256, 2) void k_ffn2(float* __restrict__ out) {
    extern __shared__ uint32_t sm[];
    __shared__ int   s_tok[128];
    __shared__ float s_wgt[128];

    int e    = blockIdx.z;
    int row0 = blockIdx.x * 128;
    int n0   = blockIdx.y * 64;
    int ne   = min(g_cnt[e], CAP);
    if (row0 >= ne) return;

    int tid = threadIdx.x;
    if (tid < 128) {
        s_tok[tid] = g_tok[e * CAPP + row0 + tid];
        s_wgt[tid] = g_wgt[e * CAPP + row0 + tid];
    }
    __syncthreads();

    const uint32_t* hin = g_h   + (size_t)e * CAPP * FDIM;
    const uint32_t* w2e = g_w2t + (size_t)e * HDIM * FDIM;

    const uint32_t* a_src[4];
    uint32_t a_dst[4];
#pragma unroll
    for (int r4 = 0; r4 < 4; r4++) {
        int idx = tid + 256 * r4;
        int row = idx >> 3, c4 = idx & 7;
        a_src[r4] = hin + (size_t)(row0 + row) * FDIM + c4 * 4;
        a_dst[r4] = sptr(sm + row * 36 + c4 * 4);
    }
    const uint32_t* b_src[2];
    uint32_t b_dst[2];
#pragma unroll
    for (int r4 = 0; r4 < 2; r4++) {
        int idx = tid + 256 * r4;
        int n = idx >> 3, c4 = idx & 7;
        b_src[r4] = w2e + (size_t)(n0 + n) * FDIM + c4 * 4;
        b_dst[r4] = sptr(sm + F2_AST + n * 36 + c4 * 4);
    }

    int warp = tid >> 5, lane = tid & 31;
    int wm = warp >> 1, wn = warp & 1;
    int g = lane >> 2, tg = lane & 3;

    float acc[2][4][4];
#pragma unroll
    for (int mi = 0; mi < 2; mi++)
#pragma unroll
        for (int ni = 0; ni < 4; ni++)
#pragma unroll
            for (int q = 0; q < 4; q++) acc[mi][ni][q] = 0.f;

#pragma unroll
    for (int t = 0; t < 2; t++) {
        int k0 = t * 32;
        uint32_t off = t * F2_STG * 4;
#pragma unroll
        for (int r4 = 0; r4 < 4; r4++) CP16(a_dst[r4] + off, a_src[r4] + k0);
#pragma unroll
        for (int r4 = 0; r4 < 2; r4++) CP16(b_dst[r4] + off, b_src[r4] + k0);
        CP_COMMIT();
    }

#pragma unroll 1
    for (int t = 0; t < FDIM / 32; t++) {
        CP_WAIT1();
        __syncthreads();
        int p = t & 1;
        const uint32_t* As = sm + p * F2_STG;
        const uint32_t* Bs = As + F2_AST;

#pragma unroll
        for (int kk = 0; kk < 4; kk++) {
            uint32_t a[2][4];
#pragma unroll
            for (int mi = 0; mi < 2; mi++) {
                int r = wm * 32 + mi * 16;
                a[mi][0] = As[(r + g)     * 36 + kk * 8 + tg];
                a[mi][1] = As[(r + 8 + g) * 36 + kk * 8 + tg];
                a[mi][2] = As[(r + g)     * 36 + kk * 8 + tg + 4];
                a[mi][3] = As[(r + 8 + g) * 36 + kk * 8 + tg + 4];
            }
#pragma unroll
            for (int ni = 0; ni < 4; ni++) {
                int n = wn * 32 + ni * 8 + g;
                uint32_t b0 = Bs[n * 36 + kk * 8 + tg];
                uint32_t b1 = Bs[n * 36 + kk * 8 + tg + 4];
#pragma unroll
                for (int mi = 0; mi < 2; mi++)
                    mma_tf32(acc[mi][ni][0], acc[mi][ni][1], acc[mi][ni][2], acc[mi][ni][3],
                             a[mi][0], a[mi][1], a[mi][2], a[mi][3], b0, b1);
            }
        }
        __syncthreads();

        int tn = t + 2;
        if (tn < FDIM / 32) {
            int k0 = tn * 32;
            uint32_t off = p * F2_STG * 4;
#pragma unroll
            for (int r4 = 0; r4 < 4; r4++) CP16(a_dst[r4] + off, a_src[r4] + k0);
#pragma unroll
            for (int r4 = 0; r4 < 2; r4++) CP16(b_dst[r4] + off, b_src[r4] + k0);
        }
        CP_COMMIT();
    }

#pragma unroll
    for (int mi = 0; mi < 2; mi++) {
#pragma unroll
        for (int ni = 0; ni < 4; ni++) {
            int cbase = n0 + wn * 32 + ni * 8 + tg * 2;
#pragma unroll
            for (int h = 0; h < 2; h++) {
                int rl = wm * 32 + mi * 16 + g + h * 8;
                float w = s_wgt[rl];
                if (w != 0.f) {
                    int tok = s_tok[rl];
                    atomicAdd(&out[(size_t)tok * HDIM + cbase],     acc[mi][ni][h * 2 + 0] * w);
                    atomicAdd(&out[(size_t)tok * HDIM + cbase + 1], acc[mi][ni][h * 2 + 1] * w);
                }
            }
        }
    }
}

// ---------------- launch ----------------
extern "C" void kernel_launch(void* const* d_in, const int* in_sizes, int n_in,
                              void* d_out, int out_size) {
    const float* x  = nullptr;
    const float* gw = nullptr;
    const float* wbig[3] = {nullptr, nullptr, nullptr};
    int nbig = 0;
    for (int i = 0; i < n_in; i++) {
        long long sz = in_sizes[i];
        if (sz == (long long)T_TOK * HDIM)           x = (const float*)d_in[i];
        else if (sz == (long long)NEXP * HDIM)       gw = (const float*)d_in[i];
        else if (nbig < 3)                           wbig[nbig++] = (const float*)d_in[i];
    }
    const float* w1 = wbig[0];
    const float* w2 = wbig[1];
    const float* w3 = wbig[2];
    float* out = (float*)d_out;

    cudaFuncSetAttribute(k_ffn1, cudaFuncAttributeMaxDynamicSharedMemorySize, F1_SMEM);
    cudaFuncSetAttribute(k_ffn2, cudaFuncAttributeMaxDynamicSharedMemorySize, F2_SMEM);

    uint32_t* w1t; cudaGetSymbolAddress((void**)&w1t, g_w1t);
    uint32_t* w2t; cudaGetSymbolAddress((void**)&w2t, g_w2t);
    uint32_t* w3t; cudaGetSymbolAddress((void**)&w3t, g_w3t);

    int wn4 = NEXP * FDIM * HDIM / 4;
    k_cvt<<<(wn4 + 255) / 256, 256>>>((const float4*)w1, (uint4*)w1t, wn4);
    k_cvt<<<(wn4 + 255) / 256, 256>>>((const float4*)w2, (uint4*)w2t, wn4);
    k_cvt<<<(wn4 + 255) / 256, 256>>>((const float4*)w3, (uint4*)w3t, wn4);

    int n4 = T_TOK * HDIM / 4;
    k_zero<<<(n4 + 255) / 256, 256>>>((float4*)out, n4);
    k_gate<<<T_TOK / 8, 256>>>(x, gw);
    k_scan<<<1, 1024>>>();
    k_ffn1<<<dim3(CAPP / 128, FDIM / 64, NEXP), 256, F1_SMEM>>>(x);
    k_ffn2<<<dim3(CAPP / 128, HDIM / 64, NEXP), 256, F2_SMEM>>>(out);
}

// round 4
// speedup vs baseline: 1.5238x; 1.0055x over previous
#include <cuda_runtime.h>
#include <cuda_bf16.h>
#include <cstdint>
#include <math.h>

#define T_TOK 16384
#define HDIM  2048
#define FDIM  256
#define NEXP  12
#define CAP   1707
#define CAPP  1792   // 14 * 128
#define LG2T  14

// ---------------- scratch (device globals; no allocs allowed) ----------------
__device__ float g_rw [T_TOK * 2];
__device__ int   g_sel[T_TOK * 2];
__device__ int   g_tok[NEXP * CAPP];
__device__ float g_wgt[NEXP * CAPP];
__device__ int   g_cnt[NEXP];
__device__ __align__(16) uint32_t g_h  [NEXP * CAPP * FDIM];      // tf32 intermediate
__device__ __align__(16) uint32_t g_w1t[NEXP * FDIM * HDIM];      // tf32 weights
__device__ __align__(16) uint32_t g_w2t[NEXP * HDIM * FDIM];
__device__ __align__(16) uint32_t g_w3t[NEXP * FDIM * HDIM];

// ---------------- helpers ----------------
__device__ __forceinline__ uint32_t f2tf(float f) {
    uint32_t u;
    asm("cvt.rna.tf32.f32 %0, %1;" : "=r"(u) : "f"(f));
    return u;
}

__device__ __forceinline__ void mma_tf32(float& d0, float& d1, float& d2, float& d3,
                                         uint32_t a0, uint32_t a1, uint32_t a2, uint32_t a3,
                                         uint32_t b0, uint32_t b1) {
    asm volatile(
        "mma.sync.aligned.m16n8k8.row.col.f32.tf32.tf32.f32 "
        "{%0,%1,%2,%3}, {%4,%5,%6,%7}, {%8,%9}, {%0,%1,%2,%3};"
        : "+f"(d0), "+f"(d1), "+f"(d2), "+f"(d3)
        : "r"(a0), "r"(a1), "r"(a2), "r"(a3), "r"(b0), "r"(b1));
}

__device__ __forceinline__ uint32_t sptr(const void* p) {
    return (uint32_t)__cvta_generic_to_shared(p);
}

#define CP16(dst_u32, src_ptr) \
    asm volatile("cp.async.cg.shared.global [%0], [%1], 16;" :: "r"(dst_u32), "l"(src_ptr))
#define CP_COMMIT() asm volatile("cp.async.commit_group;")
#define CP_WAIT2()  asm volatile("cp.async.wait_group 2;")

// ---------------- kernel 0: zero output ----------------
__global__ void k_zero(float4* out, int n4) {
    int i = blockIdx.x * blockDim.x + threadIdx.x;
    if (i < n4) out[i] = make_float4(0.f, 0.f, 0.f, 0.f);
}

// ---------------- kernel 0b: convert one weight tensor fp32 -> tf32 ----------------
__global__ void k_cvt(const float4* __restrict__ src, uint4* __restrict__ dst, int n4) {
    int i = blockIdx.x * blockDim.x + threadIdx.x;
    if (i < n4) {
        float4 v = src[i];
        uint4 u;
        u.x = f2tf(v.x); u.y = f2tf(v.y); u.z = f2tf(v.z); u.w = f2tf(v.w);
        dst[i] = u;
    }
}

// ---------------- kernel 1: gating (one warp per token) ----------------
__global__ __launch_bounds__(256) void k_gate(const float* __restrict__ x,
                                              const float* __restrict__ gw) {
    int warp = (blockIdx.x * blockDim.x + threadIdx.x) >> 5;
    int lane = threadIdx.x & 31;
    if (warp >= T_TOK) return;
    const float4* xr = (const float4*)(x + (size_t)warp * HDIM);

    float acc[NEXP];
#pragma unroll
    for (int e = 0; e < NEXP; e++) acc[e] = 0.f;

    for (int h4 = lane; h4 < HDIM / 4; h4 += 32) {
        float4 xv = xr[h4];
#pragma unroll
        for (int e = 0; e < NEXP; e++) {
            float4 gv = ((const float4*)(gw + e * HDIM))[h4];
            acc[e] += xv.x * gv.x + xv.y * gv.y + xv.z * gv.z + xv.w * gv.w;
        }
    }
#pragma unroll
    for (int e = 0; e < NEXP; e++) {
#pragma unroll
        for (int off = 16; off; off >>= 1)
            acc[e] += __shfl_xor_sync(0xffffffffu, acc[e], off);
    }
    if (lane == 0) {
        float m1 = -1e30f, m2 = -1e30f;
        int i1 = 0, i2 = 0;
#pragma unroll
        for (int e = 0; e < NEXP; e++) {
            float v = acc[e];
            if (v > m1)      { m2 = m1; i2 = i1; m1 = v; i1 = e; }
            else if (v > m2) { m2 = v;  i2 = e; }
        }
        float w1v = 1.f / (1.f + expf(m2 - m1));
        g_sel[warp * 2 + 0] = i1;
        g_sel[warp * 2 + 1] = i2;
        g_rw [warp * 2 + 0] = w1v;
        g_rw [warp * 2 + 1] = 1.f - w1v;
    }
}

// ---------------- kernel 2: order-preserving dispatch scan ----------------
__global__ __launch_bounds__(1024) void k_scan() {
    __shared__ int s[1024 * NEXP];   // 48 KB
    int j = threadIdx.x;

    for (int i = j; i < NEXP * CAPP; i += 1024) {
        g_tok[i] = 0;
        g_wgt[i] = 0.f;
    }

    int base = j * 32;
    int myexp[32];
    int cnt[NEXP];
#pragma unroll
    for (int e = 0; e < NEXP; e++) cnt[e] = 0;

#pragma unroll
    for (int q = 0; q < 32; q++) {
        int i = base + q;
        int t = i & (T_TOK - 1);
        int k = i >> LG2T;
        int e = g_sel[t * 2 + k];
        myexp[q] = e;
#pragma unroll
        for (int ee = 0; ee < NEXP; ee++) cnt[ee] += (ee == e);
    }

    int run[NEXP];
#pragma unroll
    for (int e = 0; e < NEXP; e++) { run[e] = cnt[e]; s[j * NEXP + e] = run[e]; }
    __syncthreads();

    for (int d = 1; d < 1024; d <<= 1) {
        int tmp[NEXP];
#pragma unroll
        for (int e = 0; e < NEXP; e++) tmp[e] = (j >= d) ? s[(j - d) * NEXP + e] : 0;
        __syncthreads();
#pragma unroll
        for (int e = 0; e < NEXP; e++) { run[e] += tmp[e]; s[j * NEXP + e] = run[e]; }
        __syncthreads();
    }

    if (j == 1023) {
#pragma unroll
        for (int e = 0; e < NEXP; e++) g_cnt[e] = run[e];
    }

    int off[NEXP];
#pragma unroll
    for (int e = 0; e < NEXP; e++) off[e] = run[e] - cnt[e];

#pragma unroll
    for (int q = 0; q < 32; q++) {
        int i = base + q;
        int t = i & (T_TOK - 1);
        int k = i >> LG2T;
        int e = myexp[q];
        int pos = 0;
#pragma unroll
        for (int ee = 0; ee < NEXP; ee++)
            if (ee == e) { pos = off[ee]; off[ee]++; }
        if (pos < CAP) {
            g_tok[e * CAPP + pos] = t;
            g_wgt[e * CAPP + pos] = g_rw[t * 2 + k];
        }
    }
}

// ---------------- kernel 3: GEMM1 (cp.async 3-stage pipeline) ----------------
// h = silu((x@w1^T) * (x@w3^T)); block 128x64, BK=32, 8 warps (4x2), warp 32x32.
#define F1_AST 4608            // 128*36 uint32
#define F1_BST 4608            // 2*64*36
#define F1_STG (F1_AST + F1_BST)
#define F1_SMEM (3 * F1_STG * 4)

__global__ __launch_bounds__(256, 2) void k_ffn1(const float* __restrict__ x) {
    extern __shared__ uint32_t sm[];
    __shared__ int s_tok[128];

    int e    = blockIdx.z;
    int row0 = blockIdx.x * 128;
    int n0   = blockIdx.y * 64;
    int ne   = min(g_cnt[e], CAP);
    uint32_t* hout = g_h + (size_t)e * CAPP * FDIM;

    if (row0 >= ne) {
        for (int i = threadIdx.x; i < 128 * 64; i += 256) {
            int r = i >> 6, c = i & 63;
            hout[(size_t)(row0 + r) * FDIM + n0 + c] = 0u;
        }
        return;
    }

    int tid = threadIdx.x;
    if (tid < 128) s_tok[tid] = g_tok[e * CAPP + row0 + tid];
    __syncthreads();

    const uint32_t* w1e = g_w1t + (size_t)e * FDIM * HDIM;
    const uint32_t* w3e = g_w3t + (size_t)e * FDIM * HDIM;

    int a_row[4], a_c4[4];
    const uint32_t* b_src[4];
    uint32_t a_dst[4], b_dst[4];
#pragma unroll
    for (int r4 = 0; r4 < 4; r4++) {
        int idx = tid + 256 * r4;
        a_row[r4] = idx >> 3;
        a_c4 [r4] = idx & 7;
        a_dst[r4] = sptr(sm + a_row[r4] * 36 + a_c4[r4] * 4);
        int m = idx >> 9, rem = idx & 511;
        int n = rem >> 3, c4 = rem & 7;
        b_src[r4] = ((m == 0) ? w1e : w3e) + (size_t)(n0 + n) * HDIM + c4 * 4;
        b_dst[r4] = sptr(sm + F1_AST + (m * 64 + n) * 36 + c4 * 4);
    }

    int warp = tid >> 5, lane = tid & 31;
    int wm = warp >> 1, wn = warp & 1;
    int g = lane >> 2, tg = lane & 3;

    float accA[2][4][4], accB[2][4][4];
#pragma unroll
    for (int mi = 0; mi < 2; mi++)
#pragma unroll
        for (int ni = 0; ni < 4; ni++)
#pragma unroll
            for (int q = 0; q < 4; q++) { accA[mi][ni][q] = 0.f; accB[mi][ni][q] = 0.f; }

    // prologue: stage tiles 0,1,2
#pragma unroll
    for (int t = 0; t < 3; t++) {
        int k0 = t * 32;
        uint32_t off = t * F1_STG * 4;
#pragma unroll
        for (int r4 = 0; r4 < 4; r4++) {
            CP16(a_dst[r4] + off, x + (size_t)s_tok[a_row[r4]] * HDIM + k0 + a_c4[r4] * 4);
            CP16(b_dst[r4] + off, b_src[r4] + k0);
        }
        CP_COMMIT();
    }

    const int NT = HDIM / 32;
#pragma unroll 1
    for (int t = 0; t < NT; t++) {
        CP_WAIT2();
        __syncthreads();
        int p = t % 3;
        const uint32_t* As = sm + p * F1_STG;
        const uint32_t* Bs = As + F1_AST;

#pragma unroll
        for (int kk = 0; kk < 4; kk++) {
            uint32_t a[2][4];
#pragma unroll
            for (int mi = 0; mi < 2; mi++) {
                int r = wm * 32 + mi * 16;
                a[mi][0] = f2tf(__uint_as_float(As[(r + g)     * 36 + kk * 8 + tg]));
                a[mi][1] = f2tf(__uint_as_float(As[(r + 8 + g) * 36 + kk * 8 + tg]));
                a[mi][2] = f2tf(__uint_as_float(As[(r + g)     * 36 + kk * 8 + tg + 4]));
                a[mi][3] = f2tf(__uint_as_float(As[(r + 8 + g) * 36 + kk * 8 + tg + 4]));
            }
#pragma unroll
            for (int ni = 0; ni < 4; ni++) {
                int n = wn * 32 + ni * 8 + g;
                uint32_t b0 = Bs[n * 36 + kk * 8 + tg];
                uint32_t b1 = Bs[n * 36 + kk * 8 + tg + 4];
                uint32_t c0 = Bs[(64 + n) * 36 + kk * 8 + tg];
                uint32_t c1 = Bs[(64 + n) * 36 + kk * 8 + tg + 4];
#pragma unroll
                for (int mi = 0; mi < 2; mi++) {
                    mma_tf32(accA[mi][ni][0], accA[mi][ni][1], accA[mi][ni][2], accA[mi][ni][3],
                             a[mi][0], a[mi][1], a[mi][2], a[mi][3], b0, b1);
                    mma_tf32(accB[mi][ni][0], accB[mi][ni][1], accB[mi][ni][2], accB[mi][ni][3],
                             a[mi][0], a[mi][1], a[mi][2], a[mi][3], c0, c1);
                }
            }
        }
        __syncthreads();

        int tn = t + 3;
        if (tn < NT) {
            int k0 = tn * 32;
            uint32_t off = p * F1_STG * 4;
#pragma unroll
            for (int r4 = 0; r4 < 4; r4++) {
                CP16(a_dst[r4] + off, x + (size_t)s_tok[a_row[r4]] * HDIM + k0 + a_c4[r4] * 4);
                CP16(b_dst[r4] + off, b_src[r4] + k0);
            }
        }
        CP_COMMIT();
    }

    // epilogue: h = silu(a*b) stored as tf32
#pragma unroll
    for (int mi = 0; mi < 2; mi++) {
#pragma unroll
        for (int ni = 0; ni < 4; ni++) {
            int rbase = row0 + wm * 32 + mi * 16 + g;
            int cbase = n0 + wn * 32 + ni * 8 + tg * 2;
#pragma unroll
            for (int h = 0; h < 2; h++) {
                int r = rbase + h * 8;
                float p0 = accA[mi][ni][h * 2 + 0] * accB[mi][ni][h * 2 + 0];
                float p1 = accA[mi][ni][h * 2 + 1] * accB[mi][ni][h * 2 + 1];
                float s0 = p0 / (1.f + expf(-p0));
                float s1 = p1 / (1.f + expf(-p1));
                hout[(size_t)r * FDIM + cbase]     = f2tf(s0);
                hout[(size_t)r * FDIM + cbase + 1] = f2tf(s1);
            }
        }
    }
}

// ---------------- kernel 4: GEMM2 (3-stage, N=128 tiles) + weighted atomic scatter ----------------
#define F2_AST 4608            // 128*36
#define F2_BST 4608            // 128*36
#define F2_STG (F2_AST + F2_BST)
#define F2_SMEM (3 * F2_STG * 4)

__global__ __launch_bounds__(256, 2) void k_ffn2(float* __restrict__ out) {
    extern __shared__ uint32_t sm[];
    __shared__ int   s_tok[128];
    __shared__ float s_wgt[128];

    int e    = blockIdx.z;
    int row0 = blockIdx.x * 128;
    int n0   = blockIdx.y * 128;
    int ne   = min(g_cnt[e], CAP);
    if (row0 >= ne) return;

    int tid = threadIdx.x;
    if (tid < 128) {
        s_tok[tid] = g_tok[e * CAPP + row0 + tid];
        s_wgt[tid] = g_wgt[e * CAPP + row0 + tid];
    }
    __syncthreads();

    const uint32_t* hin = g_h   + (size_t)e * CAPP * FDIM;
    const uint32_t* w2e = g_w2t + (size_t)e * HDIM * FDIM;

    const uint32_t* a_src[4];
    uint32_t a_dst[4];
    const uint32_t* b_src[4];
    uint32_t b_dst[4];
#pragma unroll
    for (int r4 = 0; r4 < 4; r4++) {
        int idx = tid + 256 * r4;
        int row = idx >> 3, c4 = idx & 7;
        a_src[r4] = hin + (size_t)(row0 + row) * FDIM + c4 * 4;
        a_dst[r4] = sptr(sm + row * 36 + c4 * 4);
        b_src[r4] = w2e + (size_t)(n0 + row) * FDIM + c4 * 4;
        b_dst[r4] = sptr(sm + F2_AST + row * 36 + c4 * 4);
    }

    int warp = tid >> 5, lane = tid & 31;
    int wm = warp >> 1, wn = warp & 1;     // 4 x 2 warps; warp tile 32 (M) x 64 (N)
    int g = lane >> 2, tg = lane & 3;

    float acc[2][8][4];
#pragma unroll
    for (int mi = 0; mi < 2; mi++)
#pragma unroll
        for (int ni = 0; ni < 8; ni++)
#pragma unroll
            for (int q = 0; q < 4; q++) acc[mi][ni][q] = 0.f;

#pragma unroll
    for (int t = 0; t < 3; t++) {
        int k0 = t * 32;
        uint32_t off = t * F2_STG * 4;
#pragma unroll
        for (int r4 = 0; r4 < 4; r4++) {
            CP16(a_dst[r4] + off, a_src[r4] + k0);
            CP16(b_dst[r4] + off, b_src[r4] + k0);
        }
        CP_COMMIT();
    }

    const int NT = FDIM / 32;
#pragma unroll 1
    for (int t = 0; t < NT; t++) {
        CP_WAIT2();
        __syncthreads();
        int p = t % 3;
        const uint32_t* As = sm + p * F2_STG;
        const uint32_t* Bs = As + F2_AST;

#pragma unroll
        for (int kk = 0; kk < 4; kk++) {
            uint32_t a[2][4];
#pragma unroll
            for (int mi = 0; mi < 2; mi++) {
                int r = wm * 32 + mi * 16;
                a[mi][0] = As[(r + g)     * 36 + kk * 8 + tg];
                a[mi][1] = As[(r + 8 + g) * 36 + kk * 8 + tg];
                a[mi][2] = As[(r + g)     * 36 + kk * 8 + tg + 4];
                a[mi][3] = As[(r + 8 + g) * 36 + kk * 8 + tg + 4];
            }
#pragma unroll
            for (int ni = 0; ni < 8; ni++) {
                int n = wn * 64 + ni * 8 + g;
                uint32_t b0 = Bs[n * 36 + kk * 8 + tg];
                uint32_t b1 = Bs[n * 36 + kk * 8 + tg + 4];
#pragma unroll
                for (int mi = 0; mi < 2; mi++)
                    mma_tf32(acc[mi][ni][0], acc[mi][ni][1], acc[mi][ni][2], acc[mi][ni][3],
                             a[mi][0], a[mi][1], a[mi][2], a[mi][3], b0, b1);
            }
        }
        __syncthreads();

        int tn = t + 3;
        if (tn < NT) {
            int k0 = tn * 32;
            uint32_t off = p * F2_STG * 4;
#pragma unroll
            for (int r4 = 0; r4 < 4; r4++) {
                CP16(a_dst[r4] + off, a_src[r4] + k0);
                CP16(b_dst[r4] + off, b_src[r4] + k0);
            }
        }
        CP_COMMIT();
    }

#pragma unroll
    for (int mi = 0; mi < 2; mi++) {
#pragma unroll
        for (int ni = 0; ni < 8; ni++) {
            int cbase = n0 + wn * 64 + ni * 8 + tg * 2;
#pragma unroll
            for (int h = 0; h < 2; h++) {
                int rl = wm * 32 + mi * 16 + g + h * 8;
                float w = s_wgt[rl];
                if (w != 0.f) {
                    int tok = s_tok[rl];
                    atomicAdd(&out[(size_t)tok * HDIM + cbase],     acc[mi][ni][h * 2 + 0] * w);
                    atomicAdd(&out[(size_t)tok * HDIM + cbase + 1], acc[mi][ni][h * 2 + 1] * w);
                }
            }
        }
    }
}

// ---------------- launch ----------------
extern "C" void kernel_launch(void* const* d_in, const int* in_sizes, int n_in,
                              void* d_out, int out_size) {
    const float* x  = nullptr;
    const float* gw = nullptr;
    const float* wbig[3] = {nullptr, nullptr, nullptr};
    int nbig = 0;
    for (int i = 0; i < n_in; i++) {
        long long sz = in_sizes[i];
        if (sz == (long long)T_TOK * HDIM)           x = (const float*)d_in[i];
        else if (sz == (long long)NEXP * HDIM)       gw = (const float*)d_in[i];
        else if (nbig < 3)                           wbig[nbig++] = (const float*)d_in[i];
    }
    const float* w1 = wbig[0];
    const float* w2 = wbig[1];
    const float* w3 = wbig[2];
    float* out = (float*)d_out;

    cudaFuncSetAttribute(k_ffn1, cudaFuncAttributeMaxDynamicSharedMemorySize, F1_SMEM);
    cudaFuncSetAttribute(k_ffn2, cudaFuncAttributeMaxDynamicSharedMemorySize, F2_SMEM);

    uint32_t* w1t; cudaGetSymbolAddress((void**)&w1t, g_w1t);
    uint32_t* w2t; cudaGetSymbolAddress((void**)&w2t, g_w2t);
    uint32_t* w3t; cudaGetSymbolAddress((void**)&w3t, g_w3t);

    int wn4 = NEXP * FDIM * HDIM / 4;
    k_cvt<<<(wn4 + 255) / 256, 256>>>((const float4*)w1, (uint4*)w1t, wn4);
    k_cvt<<<(wn4 + 255) / 256, 256>>>((const float4*)w2, (uint4*)w2t, wn4);
    k_cvt<<<(wn4 + 255) / 256, 256>>>((const float4*)w3, (uint4*)w3t, wn4);

    int n4 = T_TOK * HDIM / 4;
    k_zero<<<(n4 + 255) / 256, 256>>>((float4*)out, n4);
    k_gate<<<T_TOK / 8, 256>>>(x, gw);
    k_scan<<<1, 1024>>>();
    k_ffn1<<<dim3(CAPP / 128, FDIM / 64, NEXP), 256, F1_SMEM>>>(x);
    k_ffn2<<<dim3(CAPP / 128, HDIM / 128, NEXP), 256, F2_SMEM>>>(out);
}

// round 6
// speedup vs baseline: 1.6296x; 1.0694x over previous
#include <cuda_runtime.h>
#include <cuda_bf16.h>
#include <cstdint>
#include <math.h>

#define T_TOK 16384
#define HDIM  2048
#define FDIM  256
#define NEXP  12
#define CAP   1707
#define CAPP  1792   // 14 * 128
#define LG2T  14

// ---------------- scratch (device globals; no allocs allowed) ----------------
__device__ float g_rw [T_TOK * 2];
__device__ int   g_sel[T_TOK * 2];
__device__ int   g_tok[NEXP * CAPP];
__device__ float g_wgt[NEXP * CAPP];
__device__ int   g_cnt[NEXP];
__device__ __align__(16) uint32_t g_h  [NEXP * CAPP * FDIM];      // tf32 intermediate
__device__ __align__(16) uint32_t g_w1t[NEXP * FDIM * HDIM];      // tf32 weights
__device__ __align__(16) uint32_t g_w2t[NEXP * HDIM * FDIM];
__device__ __align__(16) uint32_t g_w3t[NEXP * FDIM * HDIM];

// ---------------- helpers ----------------
__device__ __forceinline__ uint32_t f2tf(float f) {
    uint32_t u;
    asm("cvt.rna.tf32.f32 %0, %1;" : "=r"(u) : "f"(f));
    return u;
}

__device__ __forceinline__ void mma_tf32(float& d0, float& d1, float& d2, float& d3,
                                         uint32_t a0, uint32_t a1, uint32_t a2, uint32_t a3,
                                         uint32_t b0, uint32_t b1) {
    asm volatile(
        "mma.sync.aligned.m16n8k8.row.col.f32.tf32.tf32.f32 "
        "{%0,%1,%2,%3}, {%4,%5,%6,%7}, {%8,%9}, {%0,%1,%2,%3};"
        : "+f"(d0), "+f"(d1), "+f"(d2), "+f"(d3)
        : "r"(a0), "r"(a1), "r"(a2), "r"(a3), "r"(b0), "r"(b1));
}

__device__ __forceinline__ uint32_t sptr(const void* p) {
    return (uint32_t)__cvta_generic_to_shared(p);
}

#define CP16(dst_u32, src_ptr) \
    asm volatile("cp.async.cg.shared.global [%0], [%1], 16;" :: "r"(dst_u32), "l"(src_ptr))
#define CP_COMMIT() asm volatile("cp.async.commit_group;")
#define CP_WAIT1()  asm volatile("cp.async.wait_group 1;")

// ---------------- kernel 0: zero output ----------------
__global__ void k_zero(float4* out, int n4) {
    int i = blockIdx.x * blockDim.x + threadIdx.x;
    if (i < n4) out[i] = make_float4(0.f, 0.f, 0.f, 0.f);
}

// ---------------- kernel 0b: convert one weight tensor fp32 -> tf32 ----------------
__global__ void k_cvt(const float4* __restrict__ src, uint4* __restrict__ dst, int n4) {
    int i = blockIdx.x * blockDim.x + threadIdx.x;
    if (i < n4) {
        float4 v = src[i];
        uint4 u;
        u.x = f2tf(v.x); u.y = f2tf(v.y); u.z = f2tf(v.z); u.w = f2tf(v.w);
        dst[i] = u;
    }
}

// ---------------- kernel 1: gating (one warp per token) ----------------
__global__ __launch_bounds__(256) void k_gate(const float* __restrict__ x,
                                              const float* __restrict__ gw) {
    int warp = (blockIdx.x * blockDim.x + threadIdx.x) >> 5;
    int lane = threadIdx.x & 31;
    if (warp >= T_TOK) return;
    const float4* xr = (const float4*)(x + (size_t)warp * HDIM);

    float acc[NEXP];
#pragma unroll
    for (int e = 0; e < NEXP; e++) acc[e] = 0.f;
    for (int h4 = lane; h4 < HDIM / 4; h4 += 32) {
        float4 xv = xr[h4];
#pragma unroll
        for (int e = 0; e < NEXP; e++) {
            float4 gv = ((const float4*)(gw + e * HDIM))[h4];
            acc[e] += xv.x * gv.x + xv.y * gv.y + xv.z * gv.z + xv.w * gv.w;
        }
    }
#pragma unroll
    for (int e = 0; e < NEXP; e++) {
#pragma unroll
        for (int off = 16; off; off >>= 1)
            acc[e] += __shfl_xor_sync(0xffffffffu, acc[e], off);
    }
    if (lane == 0) {
        float m1 = -1e30f, m2 = -1e30f;
        int i1 = 0, i2 = 0;
#pragma unroll
        for (int e = 0; e < NEXP; e++) {
            float v = acc[e];
            if (v > m1)      { m2 = m1; i2 = i1; m1 = v; i1 = e; }
            else if (v > m2) { m2 = v;  i2 = e; }
        }
        float w1v = 1.f / (1.f + expf(m2 - m1));
        g_sel[warp * 2 + 0] = i1;
        g_sel[warp * 2 + 1] = i2;
        g_rw [warp * 2 + 0] = w1v;
        g_rw [warp * 2 + 1] = 1.f - w1v;
    }
}

// ---------------- kernel 2: order-preserving dispatch scan ----------------
__global__ __launch_bounds__(1024) void k_scan() {
    __shared__ int s[1024 * NEXP];
    int j = threadIdx.x;
    for (int i = j; i < NEXP * CAPP; i += 1024) { g_tok[i] = 0; g_wgt[i] = 0.f; }

    int base = j * 32;
    int myexp[32];
    int cnt[NEXP];
#pragma unroll
    for (int e = 0; e < NEXP; e++) cnt[e] = 0;
#pragma unroll
    for (int q = 0; q < 32; q++) {
        int i = base + q;
        int t = i & (T_TOK - 1);
        int k = i >> LG2T;
        int e = g_sel[t * 2 + k];
        myexp[q] = e;
#pragma unroll
        for (int ee = 0; ee < NEXP; ee++) cnt[ee] += (ee == e);
    }
    int run[NEXP];
#pragma unroll
    for (int e = 0; e < NEXP; e++) { run[e] = cnt[e]; s[j * NEXP + e] = run[e]; }
    __syncthreads();
    for (int d = 1; d < 1024; d <<= 1) {
        int tmp[NEXP];
#pragma unroll
        for (int e = 0; e < NEXP; e++) tmp[e] = (j >= d) ? s[(j - d) * NEXP + e] : 0;
        __syncthreads();
#pragma unroll
        for (int e = 0; e < NEXP; e++) { run[e] += tmp[e]; s[j * NEXP + e] = run[e]; }
        __syncthreads();
    }
    if (j == 1023) {
#pragma unroll
        for (int e = 0; e < NEXP; e++) g_cnt[e] = run[e];
    }
    int off[NEXP];
#pragma unroll
    for (int e = 0; e < NEXP; e++) off[e] = run[e] - cnt[e];
#pragma unroll
    for (int q = 0; q < 32; q++) {
        int i = base + q;
        int t = i & (T_TOK - 1);
        int k = i >> LG2T;
        int e = myexp[q];
        int pos = 0;
#pragma unroll
        for (int ee = 0; ee < NEXP; ee++)
            if (ee == e) { pos = off[ee]; off[ee]++; }
        if (pos < CAP) {
            g_tok[e * CAPP + pos] = t;
            g_wgt[e * CAPP + pos] = g_rw[t * 2 + k];
        }
    }
}

// ---------------- kernel 3: GEMM1 — 128 thr, block 128x64(x2 ops), warp 64x32, mi=4 ----------------
#define F1_AST 4608            // 128*36 uint32
#define F1_BST 4608            // 2*64*36
#define F1_STG (F1_AST + F1_BST)
#define F1_SMEM (2 * F1_STG * 4)

__global__ __launch_bounds__(128, 2) void k_ffn1(const float* __restrict__ x) {
    extern __shared__ uint32_t sm[];
    __shared__ int s_tok[128];

    int e    = blockIdx.z;
    int row0 = blockIdx.x * 128;
    int n0   = blockIdx.y * 64;
    int ne   = min(g_cnt[e], CAP);
    if (row0 >= ne) return;   // ffn2 skips the same tiles
    uint32_t* hout = g_h + (size_t)e * CAPP * FDIM;

    int tid = threadIdx.x;
    s_tok[tid] = g_tok[e * CAPP + row0 + tid];
    __syncthreads();

    const uint32_t* w1e = g_w1t + (size_t)e * FDIM * HDIM;
    const uint32_t* w3e = g_w3t + (size_t)e * FDIM * HDIM;

    // per-thread load descriptors: 8 A chunks + 8 B chunks (16B each)
    int a_row[8], a_c4[8];
    const uint32_t* b_src[8];
    uint32_t a_dst[8], b_dst[8];
#pragma unroll
    for (int u = 0; u < 8; u++) {
        int idx = tid + 128 * u;
        a_row[u] = idx >> 3;
        a_c4 [u] = idx & 7;
        a_dst[u] = sptr(sm + a_row[u] * 36 + a_c4[u] * 4);
        int m = idx >> 9, rem = idx & 511;     // m: 0 = w1, 1 = w3
        int n = rem >> 3, c4 = rem & 7;
        b_src[u] = ((m == 0) ? w1e : w3e) + (size_t)(n0 + n) * HDIM + c4 * 4;
        b_dst[u] = sptr(sm + F1_AST + (m * 64 + n) * 36 + c4 * 4);
    }

    int warp = tid >> 5, lane = tid & 31;
    int wm = warp >> 1, wn = warp & 1;          // 2 x 2 warps, warp tile 64(M) x 32(N)
    int g = lane >> 2, tg = lane & 3;

    float accA[4][4][4], accB[4][4][4];
#pragma unroll
    for (int mi = 0; mi < 4; mi++)
#pragma unroll
        for (int ni = 0; ni < 4; ni++)
#pragma unroll
            for (int q = 0; q < 4; q++) { accA[mi][ni][q] = 0.f; accB[mi][ni][q] = 0.f; }

    // prologue: stage tiles 0,1
#pragma unroll
    for (int t = 0; t < 2; t++) {
        int k0 = t * 32;
        uint32_t off = t * F1_STG * 4;
#pragma unroll
        for (int u = 0; u < 8; u++) {
            CP16(a_dst[u] + off, x + (size_t)s_tok[a_row[u]] * HDIM + k0 + a_c4[u] * 4);
            CP16(b_dst[u] + off, b_src[u] + k0);
        }
        CP_COMMIT();
    }

    const int NT = HDIM / 32;
#pragma unroll 1
    for (int t = 0; t < NT; t++) {
        CP_WAIT1();
        __syncthreads();
        int p = t & 1;
        const uint32_t* As = sm + p * F1_STG;
        const uint32_t* Bs = As + F1_AST;

#pragma unroll
        for (int kk = 0; kk < 4; kk++) {
            uint32_t a[4][4];
#pragma unroll
            for (int mi = 0; mi < 4; mi++) {
                int r = wm * 64 + mi * 16;
                a[mi][0] = f2tf(__uint_as_float(As[(r + g)     * 36 + kk * 8 + tg]));
                a[mi][1] = f2tf(__uint_as_float(As[(r + 8 + g) * 36 + kk * 8 + tg]));
                a[mi][2] = f2tf(__uint_as_float(As[(r + g)     * 36 + kk * 8 + tg + 4]));
                a[mi][3] = f2tf(__uint_as_float(As[(r + 8 + g) * 36 + kk * 8 + tg + 4]));
            }
#pragma unroll
            for (int ni = 0; ni < 4; ni++) {
                int n = wn * 32 + ni * 8 + g;
                uint32_t b0 = Bs[n * 36 + kk * 8 + tg];
                uint32_t b1 = Bs[n * 36 + kk * 8 + tg + 4];
                uint32_t c0 = Bs[(64 + n) * 36 + kk * 8 + tg];
                uint32_t c1 = Bs[(64 + n) * 36 + kk * 8 + tg + 4];
#pragma unroll
                for (int mi = 0; mi < 4; mi++) {
                    mma_tf32(accA[mi][ni][0], accA[mi][ni][1], accA[mi][ni][2], accA[mi][ni][3],
                             a[mi][0], a[mi][1], a[mi][2], a[mi][3], b0, b1);
                    mma_tf32(accB[mi][ni][0], accB[mi][ni][1], accB[mi][ni][2], accB[mi][ni][3],
                             a[mi][0], a[mi][1], a[mi][2], a[mi][3], c0, c1);
                }
            }
        }
        __syncthreads();

        int tn = t + 2;
        if (tn < NT) {
            int k0 = tn * 32;
            uint32_t off = p * F1_STG * 4;
#pragma unroll
            for (int u = 0; u < 8; u++) {
                CP16(a_dst[u] + off, x + (size_t)s_tok[a_row[u]] * HDIM + k0 + a_c4[u] * 4);
                CP16(b_dst[u] + off, b_src[u] + k0);
            }
        }
        CP_COMMIT();
    }

    // epilogue: h = silu(a*b) stored as tf32
#pragma unroll
    for (int mi = 0; mi < 4; mi++) {
#pragma unroll
        for (int ni = 0; ni < 4; ni++) {
            int rbase = row0 + wm * 64 + mi * 16 + g;
            int cbase = n0 + wn * 32 + ni * 8 + tg * 2;
#pragma unroll
            for (int h = 0; h < 2; h++) {
                int r = rbase + h * 8;
                float p0 = accA[mi][ni][h * 2 + 0] * accB[mi][ni][h * 2 + 0];
                float p1 = accA[mi][ni][h * 2 + 1] * accB[mi][ni][h * 2 + 1];
                float s0 = p0 / (1.f + expf(-p0));
                float s1 = p1 / (1.f + expf(-p1));
                hout[(size_t)r * FDIM + cbase]     = f2tf(s0);
                hout[(size_t)r * FDIM + cbase + 1] = f2tf(s1);
            }
        }
    }
}

// ---------------- kernel 4: GEMM2 — 128 thr, block 128x128, warp 64x64, mi=4 ni=8 ----------------
#define F2_AST 4608            // 128*36
#define F2_BST 4608            // 128*36
#define F2_STG (F2_AST + F2_BST)
#define F2_SMEM (2 * F2_STG * 4)

__global__ __launch_bounds__(128, 2) void k_ffn2(float* __restrict__ out) {
    extern __shared__ uint32_t sm[];
    __shared__ int   s_tok[128];
    __shared__ float s_wgt[128];

    int e    = blockIdx.z;
    int row0 = blockIdx.x * 128;
    int n0   = blockIdx.y * 128;
    int ne   = min(g_cnt[e], CAP);
    if (row0 >= ne) return;

    int tid = threadIdx.x;
    s_tok[tid] = g_tok[e * CAPP + row0 + tid];
    s_wgt[tid] = g_wgt[e * CAPP + row0 + tid];
    __syncthreads();

    const uint32_t* hin = g_h   + (size_t)e * CAPP * FDIM;
    const uint32_t* w2e = g_w2t + (size_t)e * HDIM * FDIM;

    const uint32_t* a_src[8];
    uint32_t a_dst[8];
    const uint32_t* b_src[8];
    uint32_t b_dst[8];
#pragma unroll
    for (int u = 0; u < 8; u++) {
        int idx = tid + 128 * u;
        int row = idx >> 3, c4 = idx & 7;
        a_src[u] = hin + (size_t)(row0 + row) * FDIM + c4 * 4;
        a_dst[u] = sptr(sm + row * 36 + c4 * 4);
        b_src[u] = w2e + (size_t)(n0 + row) * FDIM + c4 * 4;
        b_dst[u] = sptr(sm + F2_AST + row * 36 + c4 * 4);
    }

    int warp = tid >> 5, lane = tid & 31;
    int wm = warp >> 1, wn = warp & 1;          // warp tile 64(M) x 64(N)
    int g = lane >> 2, tg = lane & 3;

    float acc[4][8][4];
#pragma unroll
    for (int mi = 0; mi < 4; mi++)
#pragma unroll
        for (int ni = 0; ni < 8; ni++)
#pragma unroll
            for (int q = 0; q < 4; q++) acc[mi][ni][q] = 0.f;

#pragma unroll
    for (int t = 0; t < 2; t++) {
        int k0 = t * 32;
        uint32_t off = t * F2_STG * 4;
#pragma unroll
        for (int u = 0; u < 8; u++) {
            CP16(a_dst[u] + off, a_src[u] + k0);
            CP16(b_dst[u] + off, b_src[u] + k0);
        }
        CP_COMMIT();
    }

    const int NT = FDIM / 32;
#pragma unroll 1
    for (int t = 0; t < NT; t++) {
        CP_WAIT1();
        __syncthreads();
        int p = t & 1;
        const uint32_t* As = sm + p * F2_STG;
        const uint32_t* Bs = As + F2_AST;

#pragma unroll
        for (int kk = 0; kk < 4; kk++) {
            uint32_t a[4][4];
#pragma unroll
            for (int mi = 0; mi < 4; mi++) {
                int r = wm * 64 + mi * 16;
                a[mi][0] = As[(r + g)     * 36 + kk * 8 + tg];
                a[mi][1] = As[(r + 8 + g) * 36 + kk * 8 + tg];
                a[mi][2] = As[(r + g)     * 36 + kk * 8 + tg + 4];
                a[mi][3] = As[(r + 8 + g) * 36 + kk * 8 + tg + 4];
            }
#pragma unroll
            for (int ni = 0; ni < 8; ni++) {
                int n = wn * 64 + ni * 8 + g;
                uint32_t b0 = Bs[n * 36 + kk * 8 + tg];
                uint32_t b1 = Bs[n * 36 + kk * 8 + tg + 4];
#pragma unroll
                for (int mi = 0; mi < 4; mi++)
                    mma_tf32(acc[mi][ni][0], acc[mi][ni][1], acc[mi][ni][2], acc[mi][ni][3],
                             a[mi][0], a[mi][1], a[mi][2], a[mi][3], b0, b1);
            }
        }
        __syncthreads();

        int tn = t + 2;
        if (tn < NT) {
            int k0 = tn * 32;
            uint32_t off = p * F2_STG * 4;
#pragma unroll
            for (int u = 0; u < 8; u++) {
                CP16(a_dst[u] + off, a_src[u] + k0);
                CP16(b_dst[u] + off, b_src[u] + k0);
            }
        }
        CP_COMMIT();
    }

    // epilogue: weighted atomic scatter
#pragma unroll
    for (int mi = 0; mi < 4; mi++) {
#pragma unroll
        for (int ni = 0; ni < 8; ni++) {
            int cbase = n0 + wn * 64 + ni * 8 + tg * 2;
#pragma unroll
            for (int h = 0; h < 2; h++) {
                int rl = wm * 64 + mi * 16 + g + h * 8;
                float w = s_wgt[rl];
                if (w != 0.f) {
                    int tok = s_tok[rl];
                    atomicAdd(&out[(size_t)tok * HDIM + cbase],     acc[mi][ni][h * 2 + 0] * w);
                    atomicAdd(&out[(size_t)tok * HDIM + cbase + 1], acc[mi][ni][h * 2 + 1] * w);
                }
            }
        }
    }
}

// ---------------- launch ----------------
extern "C" void kernel_launch(void* const* d_in, const int* in_sizes, int n_in,
                              void* d_out, int out_size) {
    const float* x  = nullptr;
    const float* gw = nullptr;
    const float* wbig[3] = {nullptr, nullptr, nullptr};
    int nbig = 0;
    for (int i = 0; i < n_in; i++) {
        long long sz = in_sizes[i];
        if (sz == (long long)T_TOK * HDIM)      x = (const float*)d_in[i];
        else if (sz == (long long)NEXP * HDIM)  gw = (const float*)d_in[i];
        else if (nbig < 3)                      wbig[nbig++] = (const float*)d_in[i];
    }
    const float* w1 = wbig[0];
    const float* w2 = wbig[1];
    const float* w3 = wbig[2];
    float* out = (float*)d_out;

    cudaFuncSetAttribute(k_ffn1, cudaFuncAttributeMaxDynamicSharedMemorySize, F1_SMEM);
    cudaFuncSetAttribute(k_ffn2, cudaFuncAttributeMaxDynamicSharedMemorySize, F2_SMEM);

    uint32_t* w1t; cudaGetSymbolAddress((void**)&w1t, g_w1t);
    uint32_t* w2t; cudaGetSymbolAddress((void**)&w2t, g_w2t);
    uint32_t* w3t; cudaGetSymbolAddress((void**)&w3t, g_w3t);

    int wn4 = NEXP * FDIM * HDIM / 4;
    k_cvt<<<(wn4 + 255) / 256, 256>>>((const float4*)w1, (uint4*)w1t, wn4);
    k_cvt<<<(wn4 + 255) / 256, 256>>>((const float4*)w2, (uint4*)w2t, wn4);
    k_cvt<<<(wn4 + 255) / 256, 256>>>((const float4*)w3, (uint4*)w3t, wn4);

    int n4 = T_TOK * HDIM / 4;
    k_zero<<<(n4 + 255) / 256, 256>>>((float4*)out, n4);
    k_gate<<<T_TOK / 8, 256>>>(x, gw);
    k_scan<<<1, 1024>>>();
    k_ffn1<<<dim3(CAPP / 128, FDIM / 64, NEXP), 128, F1_SMEM>>>(x);
    k_ffn2<<<dim3(CAPP / 128, HDIM / 128, NEXP), 128, F2_SMEM>>>(out);
}